// round 9
// baseline (speedup 1.0000x reference)
#include <cuda_runtime.h>
#include <cstdint>

#define BATCH 4
#define HH 384
#define WW 384
#define NN 128
#define RAD 4
#define NSTEPS 50
#define CLIPMAX 382.999f
#define HB 8
#define BW (2 * HB + 1)

// ---------------- scratch ----------------
__device__ float4 g_Gq [BATCH * HH * WW];
__device__ float4 g_GWq[BATCH * HH * WW];
__device__ float  g_M [NN * NN];
__device__ float  g_Mw[NN * NN];
__device__ float2 g_pts[BATCH * NN];
__device__ float  g_wid[BATCH * NN];
__device__ float  g_part[576];
__device__ int    g_convdone[BATCH];   // zero-init; reset by render's last block
__device__ int    g_matdone;
__device__ unsigned g_cnt;

typedef unsigned long long ull;

__device__ __forceinline__ float fsqrt_approx(float x) {
    float r; asm("sqrt.approx.f32 %0, %1;" : "=f"(r) : "f"(x)); return r;
}
__device__ __forceinline__ ull pack2(float lo, float hi) {
    ull r; asm("mov.b64 %0, {%1, %2};" : "=l"(r) : "f"(lo), "f"(hi)); return r;
}
__device__ __forceinline__ float2 unpack2(ull v) {
    float2 r; asm("mov.b64 {%0, %1}, %2;" : "=f"(r.x), "=f"(r.y) : "l"(v)); return r;
}
__device__ __forceinline__ void ffma2(ull& d, ull a, ull b) {
    asm("fma.rn.f32x2 %0, %1, %2, %0;" : "+l"(d) : "l"(a), "l"(b));
}
__device__ __forceinline__ int ld_acq(const int* p) {
    int v; asm volatile("ld.global.acquire.gpu.b32 %0, [%1];" : "=r"(v) : "l"(p)); return v;
}
// coherent L1-cached vector load (NOT the nc/read-only path)
__device__ __forceinline__ float4 ldg_ca_v4(const float4* p) {
    float4 v;
    asm volatile("ld.global.ca.v4.f32 {%0,%1,%2,%3}, [%4];"
                 : "=f"(v.x), "=f"(v.y), "=f"(v.z), "=f"(v.w) : "l"(p));
    return v;
}
// coherent L2-direct scalar load
__device__ __forceinline__ float ldg_cg_f32(const float* p) {
    float v; asm volatile("ld.global.cg.f32 %0, [%1];" : "=f"(v) : "l"(p)); return v;
}

// bilinear on quad plane with coherent loads
__device__ __forceinline__ float2 bilinq_ca(const float4* plane, float y, float x) {
    y = fminf(fmaxf(y, 0.f), CLIPMAX);
    x = fminf(fmaxf(x, 0.f), CLIPMAX);
    float fy = floorf(y), fx = floorf(x);
    int   y0 = (int)fy,  x0 = (int)fx;
    float wy = y - fy,   wx = x - fx;
    const float4* p = plane + y0 * WW + x0;
    float4 qa = ldg_ca_v4(p);
    float4 qb = ldg_ca_v4(p + 1);
    float w00 = (1.f - wy) * (1.f - wx);
    float w01 = (1.f - wy) * wx;
    float w10 = wy * (1.f - wx);
    float w11 = wy * wx;
    float2 r;
    r.x = qa.x * w00 + qb.x * w01 + qa.z * w10 + qb.z * w11;
    r.y = qa.y * w00 + qb.y * w01 + qa.w * w10 + qb.w * w11;
    return r;
}

struct ConvSmem  { float2 tile[40][40]; float4 hs[40][32]; };   // 33280 B
struct MatSmem   { float am[2][NN]; float aw[2][NN]; };
struct SnakeSmem { float2 v2pad[2][NN + 2 * HB]; float vwpad[2][NN + 2 * HB]; };

#define SMEM_BYTES 33408

// Kernel 1:  [0,4) snake | [4,68) matgen | [68,644) conv (sample-grouped).
// All 644 blocks fit in wave 1 -> snakes overlap conv; no deadlock possible.
__global__ void __launch_bounds__(256) prep_snake_kernel(const float* __restrict__ pred,
                                                         const float* __restrict__ nodes) {
    __shared__ __align__(16) char smem_u[SMEM_BYTES];
    const int bid = blockIdx.x;
    const int tid = threadIdx.x;

    if (bid >= 68) {
        // ================= conv =================
        ConvSmem& S = *reinterpret_cast<ConvSmem*>(smem_u);
        const int cid = bid - 68;
        const int b  = cid / 144;
        const int tl = cid % 144;
        const int bx = (tl % 12) * 32;
        const int by = (tl / 12) * 32;
        const float* img = pred + b * HH * WW;

        float g[9], dg[9], s = 0.f;
#pragma unroll
        for (int k = 0; k < 9; k++) { float t = (float)(k - 4); g[k] = expf(-t * t * 0.125f); s += g[k]; }
        float inv = 1.f / s;
#pragma unroll
        for (int k = 0; k < 9; k++) { g[k] *= inv; dg[k] = -(float)(k - 4) * 0.25f * g[k]; }

        for (int i = tid; i < 40 * 40; i += 256) {
            int ly = i / 40, lx = i % 40;
            int gy = by - RAD + ly, gx = bx - RAD + lx;
            float v = (gy >= 0 && gy < HH && gx >= 0 && gx < WW) ? img[gy * WW + gx] : 0.f;
            S.tile[ly][lx] = make_float2(v, fabsf(v));
        }
        __syncthreads();

        for (int i = tid; i < 40 * 32; i += 256) {
            int r = i >> 5, c = i & 31;
            float hgp = 0.f, hdp = 0.f, hga = 0.f, hda = 0.f;
#pragma unroll
            for (int kx = 0; kx < 9; kx++) {
                float2 v = S.tile[r][c + kx];
                hgp = fmaf(g[kx],  v.x, hgp);
                hdp = fmaf(dg[kx], v.x, hdp);
                hga = fmaf(g[kx],  v.y, hga);
                hda = fmaf(dg[kx], v.y, hda);
            }
            S.hs[r][c] = make_float4(hgp, hdp, hga, hda);
        }
        __syncthreads();

        const int tx = tid & 31, ty = tid >> 5;
#pragma unroll
        for (int s4 = 0; s4 < 4; s4++) {
            int oy = ty + s4 * 8;
            float c0p = 0.f, c1p = 0.f, c0a = 0.f, c1a = 0.f;
#pragma unroll
            for (int ky = 0; ky < 9; ky++) {
                float4 h = S.hs[oy + ky][tx];
                c0p = fmaf(dg[ky], h.x, c0p);
                c1p = fmaf(g[ky],  h.y, c1p);
                c0a = fmaf(dg[ky], h.z, c0a);
                c1a = fmaf(g[ky],  h.w, c1a);
            }
            const int yg = by + oy, xg = bx + tx;
            const int o  = (b * HH + yg) * WW + xg;
            float2 Gv  = make_float2(10.f * c0p, 10.f * c1p);
            float2 GWv = make_float2(10.f * c0a, 10.f * c1a);
            reinterpret_cast<float2*>(&g_Gq [o])[0] = Gv;
            reinterpret_cast<float2*>(&g_GWq[o])[0] = GWv;
            if (yg > 0) {
                reinterpret_cast<float2*>(&g_Gq [o - WW])[1] = Gv;
                reinterpret_cast<float2*>(&g_GWq[o - WW])[1] = GWv;
            }
        }
        __threadfence();
        __syncthreads();
        if (tid == 0) atomicAdd(&g_convdone[b], 1);

    } else if (bid >= 4) {
        // ================= matgen =================
        MatSmem& S = *reinterpret_cast<MatSmem*>(smem_u);
        const int h = tid >> 7;
        const int i = (bid - 4) * 2 + h;
        const int j = tid & 127;
        {
            int k = j;
            float lam = 2.f - 2.f * cospif((float)k / 128.f);
            float c2  = (k == 0 ? 1.f : 2.f) / 128.f;
            float dm  = 1.f / (1.f + 0.001f * lam + 0.001f * lam * lam);
            float dw  = 1.f / (1.f + 0.001f * lam);
            float a   = cospif((float)(k * (2 * i + 1)) / 256.f);
            S.am[h][k] = c2 * dm * a;
            S.aw[h][k] = c2 * dw * a;
        }
        __syncthreads();
        float sm = 0.f, sw = 0.f;
#pragma unroll 4
        for (int k = 0; k < NN; k++) {
            float bq = cospif((float)(k * (2 * j + 1)) / 256.f);
            sm = fmaf(S.am[h][k], bq, sm);
            sw = fmaf(S.aw[h][k], bq, sw);
        }
        g_M [i * NN + j] = sm;
        g_Mw[i * NN + j] = sw;
        __threadfence();
        __syncthreads();
        if (tid == 0) atomicAdd(&g_matdone, 1);

    } else {
        // ================= snake =================
        SnakeSmem& S = *reinterpret_cast<SnakeSmem*>(smem_u);
        const int b = bid;
        const int i = tid >> 1;
        const int h = tid & 1;

        if (tid < HB) {
#pragma unroll
            for (int s = 0; s < 2; s++) {
                S.v2pad[s][tid] = make_float2(0.f, 0.f);
                S.v2pad[s][NN + HB + tid] = make_float2(0.f, 0.f);
                S.vwpad[s][tid] = 0.f;
                S.vwpad[s][NN + HB + tid] = 0.f;
            }
        }

        // wait for this sample's conv tiles + matgen
        if (tid == 0) {
            while (ld_acq(&g_convdone[b]) < 144 || ld_acq(&g_matdone) < 64) __nanosleep(64);
        }
        __syncthreads();

        // band taps via coherent L2 loads (same-launch data; nc path is forbidden here)
        ull   Mp[9];
        float Mwr[9];
#pragma unroll
        for (int uu = 0; uu < 9; uu++) {
            int u = 2 * uu + h;
            float m = 0.f, mw = 0.f;
            if (u < BW) {
                int j = i - HB + u;
                bool ok = (j >= 0) && (j < NN);
                m  = ok ? ldg_cg_f32(&g_M [i * NN + j]) : 0.f;
                mw = ok ? ldg_cg_f32(&g_Mw[i * NN + j]) : 0.f;
            }
            Mp[uu]  = pack2(m, m);
            Mwr[uu] = mw;
        }

        const float4* Gb    = g_Gq  + b * HH * WW;
        const float4* GWb   = g_GWq + b * HH * WW;
        const float4* plane = h ? GWb : Gb;

        float2 p = make_float2(nodes[(b * NN + i) * 2], nodes[(b * NN + i) * 2 + 1]);
        float  wd = 1.f;

        float2 gres = bilinq_ca(plane, p.x, p.y);
        __syncthreads();

#pragma unroll 2
        for (int k = 1; k <= NSTEPS; k++) {
            const int buf = k & 1;
            if (h == 0)
                S.v2pad[buf][HB + i] = make_float2(p.x + 0.1f * gres.x, p.y + 0.1f * gres.y);
            else
                S.vwpad[buf][HB + i] = wd + 0.1f * sqrtf(gres.x * gres.x + gres.y * gres.y);
            __syncthreads();

            const ull* v2u = reinterpret_cast<const ull*>(S.v2pad[buf]);
            ull acc = 0ull;
#pragma unroll
            for (int uu = 0; uu < 9; uu++) {
                int u = 2 * uu + h;
                if (u < BW) ffma2(acc, Mp[uu], v2u[i + u]);
            }
            float2 pa = unpack2(acc);
            pa.x += __shfl_xor_sync(0xffffffffu, pa.x, 1);
            pa.y += __shfl_xor_sync(0xffffffffu, pa.y, 1);
            p = pa;

            gres = bilinq_ca(plane, p.x, p.y);

            const float* vw = S.vwpad[buf];
            float wacc = 0.f;
#pragma unroll
            for (int uu = 0; uu < 9; uu++) {
                int u = 2 * uu + h;
                if (u < BW) wacc = fmaf(Mwr[uu], vw[i + u], wacc);
            }
            wacc += __shfl_xor_sync(0xffffffffu, wacc, 1);
            if (k > 1) wd = wacc;
        }

        {
            const int buf = (NSTEPS + 1) & 1;
            if (h == 1)
                S.vwpad[buf][HB + i] = wd + 0.1f * sqrtf(gres.x * gres.x + gres.y * gres.y);
            __syncthreads();
            const float* vw = S.vwpad[buf];
            float wacc = 0.f;
#pragma unroll
            for (int uu = 0; uu < 9; uu++) {
                int u = 2 * uu + h;
                if (u < BW) wacc = fmaf(Mwr[uu], vw[i + u], wacc);
            }
            wacc += __shfl_xor_sync(0xffffffffu, wacc, 1);
            wd = wacc;
        }

        if (h == 0) g_pts[b * NN + i] = p;
        else        g_wid[b * NN + i] = wd;
    }
}

// Kernel 2: render + shortlist + fused final reduce (reads g_pts/g_wid across
// the launch boundary -> proven-safe). Last block resets flags for next replay.
__global__ void __launch_bounds__(256) render_kernel(const float* __restrict__ pred,
                                                     float* __restrict__ out) {
    const int b  = blockIdx.z;
    const int x0 = blockIdx.x * 32;
    const int y0 = blockIdx.y * 32;
    const int t  = threadIdx.x;

    __shared__ float4 keep[NN];
    __shared__ float  ur[NN];
    __shared__ int    wcnt[4], wofs[4], cnt;
    __shared__ float  ublim;

    float lb = 0.f; float4 nd = make_float4(0, 0, 0, 0); unsigned bmask = 0; bool pred_k = false;
    const float cy = (float)y0 + 15.5f, cx = (float)x0 + 15.5f;
    const float R = 21.95f;
    if (t < NN) {
        float2 p = g_pts[b * NN + t];
        float w  = g_wid[b * NN + t];
        nd = make_float4(p.x, p.y, w, 0.f);
        float dy = p.x - cy, dx = p.y - cx;
        float cd = sqrtf(dy * dy + dx * dx);
        lb = cd - R - w;
        ur[t] = cd + R - w;
    }
    __syncthreads();
    if (t < 64) ur[t] = fminf(ur[t], ur[t + 64]);
    __syncthreads();
    if (t < 32) {
        float v = fminf(ur[t], ur[t + 32]);
#pragma unroll
        for (int s = 16; s > 0; s >>= 1) v = fminf(v, __shfl_xor_sync(0xffffffffu, v, s));
        if (t == 0) ublim = fminf(v, 15.0f) + 0.02f;
    }
    __syncthreads();

    if (t < NN) {
        pred_k = lb < ublim;
        bmask = __ballot_sync(0xffffffffu, pred_k);
        if ((t & 31) == 0) wcnt[t >> 5] = __popc(bmask);
    }
    __syncthreads();
    if (t == 0) {
        int o = 0;
#pragma unroll
        for (int w = 0; w < 4; w++) { wofs[w] = o; o += wcnt[w]; }
        cnt = o;
    }
    __syncthreads();
    if (t < NN && pred_k) {
        int pos = wofs[t >> 5] + __popc(bmask & ((1u << (t & 31)) - 1u));
        keep[pos] = nd;
    }
    __syncthreads();

    const int n = cnt;
    const int y  = y0 + (t >> 3);
    const int xg = x0 + (t & 7) * 4;
    const float fy = (float)y, fx0 = (float)xg;
    const float mub = ublim;
    float m0 = mub, m1 = mub, m2 = mub, m3 = mub;

    for (int k = 0; k < n; k++) {
        float4 kk = keep[k];
        float dy  = fy - kk.x;
        float dy2 = dy * dy;
        float dx0 = fx0 - kk.y;
        float dx1 = dx0 + 1.f, dx2 = dx0 + 2.f, dx3 = dx0 + 3.f;
        float d20 = fmaf(dx0, dx0, dy2);
        float d21 = fmaf(dx1, dx1, dy2);
        float d22 = fmaf(dx2, dx2, dy2);
        float d23 = fmaf(dx3, dx3, dy2);
        float t0 = m0 + kk.z, t1 = m1 + kk.z, t2 = m2 + kk.z, t3 = m3 + kk.z;
        bool imp = (t0 > 0.f && d20 < t0 * t0) || (t1 > 0.f && d21 < t1 * t1) ||
                   (t2 > 0.f && d22 < t2 * t2) || (t3 > 0.f && d23 < t3 * t3);
        if (__any_sync(0xffffffffu, imp)) {
            m0 = fminf(m0, fsqrt_approx(d20) - kk.z);
            m1 = fminf(m1, fsqrt_approx(d21) - kk.z);
            m2 = fminf(m2, fsqrt_approx(d22) - kk.z);
            m3 = fminf(m3, fsqrt_approx(d23) - kk.z);
        }
    }
    m0 = fminf(fmaxf(m0, 0.f), 15.f);
    m1 = fminf(fmaxf(m1, 0.f), 15.f);
    m2 = fminf(fmaxf(m2, 0.f), 15.f);
    m3 = fminf(fmaxf(m3, 0.f), 15.f);

    const float4 pv = *reinterpret_cast<const float4*>(pred + (b * HH + y) * WW + xg);
    float e0 = pv.x - m0, e1 = pv.y - m1, e2 = pv.z - m2, e3 = pv.w - m3;
    float e = e0 * e0 + e1 * e1 + e2 * e2 + e3 * e3;

    __shared__ float red[256];
    red[t] = e;
    __syncthreads();
    if (t < 128) red[t] += red[t + 128];
    __syncthreads();
    if (t < 64) red[t] += red[t + 64];
    __syncthreads();
    if (t < 32) {
        float v = red[t] + red[t + 32];
#pragma unroll
        for (int s = 16; s > 0; s >>= 1) v += __shfl_down_sync(0xffffffffu, v, s);
        if (t == 0) g_part[(b * 12 + blockIdx.y) * 12 + blockIdx.x] = v;
    }

    __shared__ bool amLast;
    if (t == 0) {
        __threadfence();
        unsigned v = atomicAdd(&g_cnt, 1u);
        amLast = (v == 575u);
    }
    __syncthreads();
    if (amLast) {
        __shared__ double sh[256];
        double s = 0.0;
        for (int idx = t; idx < 576; idx += 256) s += (double)g_part[idx];
        sh[t] = s;
        __syncthreads();
        for (int st = 128; st > 0; st >>= 1) {
            if (t < st) sh[t] += sh[t + st];
            __syncthreads();
        }
        if (t == 0) {
            out[0] = (float)(sh[0] / (double)(BATCH * HH * WW));
            // reset flags for the next graph replay (stream-ordered before it)
            g_cnt = 0u;
            g_matdone = 0;
#pragma unroll
            for (int q = 0; q < BATCH; q++) g_convdone[q] = 0;
        }
    }
}

// ---------------- launcher ----------------
extern "C" void kernel_launch(void* const* d_in, const int* in_sizes, int n_in,
                              void* d_out, int out_size) {
    const float* pred  = (const float*)d_in[0];
    const float* nodes = (const float*)d_in[1];
    float* out = (float*)d_out;
    (void)in_sizes; (void)n_in; (void)out_size;

    prep_snake_kernel<<<644, 256>>>(pred, nodes);
    render_kernel<<<dim3(12, 12, BATCH), 256>>>(pred, out);
}

// round 10
// speedup vs baseline: 1.0223x; 1.0223x over previous
#include <cuda_runtime.h>
#include <cstdint>

#define BATCH 4
#define HH 384
#define WW 384
#define NN 128
#define RAD 4
#define NSTEPS 50
#define CLIPMAX 382.999f
#define HB 8
#define BW (2 * HB + 1)

// ---------------- scratch ----------------
__device__ float4 g_Gq [BATCH * HH * WW];
__device__ float4 g_GWq[BATCH * HH * WW];
__device__ float  g_M [NN * NN];
__device__ float  g_Mw[NN * NN];
__device__ float2 g_pts[BATCH * NN];
__device__ float  g_wid[BATCH * NN];
__device__ float  g_part[576];
__device__ int    g_snakeflag[BATCH];   // zero-init; reset by last render block
__device__ unsigned g_cnt;

typedef unsigned long long ull;

// conv weights (float64-accurate literals; numpy float32 pipeline deviates < 1e-7)
__device__ __constant__ float C_G[9] = {
    0.027630550874912204f, 0.06628226552596338f, 0.12383156996112883f,
    0.18017411419619135f,  0.20416299888360846f, 0.18017411419619135f,
    0.12383156996112883f,  0.06628226552596338f, 0.027630550874912204f };
__device__ __constant__ float C_DG[9] = {
    0.027630550874912204f,  0.049711699144472535f,  0.061915784980564414f,
    0.04504352854904784f,   0.0f,                  -0.04504352854904784f,
   -0.061915784980564414f, -0.049711699144472535f, -0.027630550874912204f };

__device__ __forceinline__ float fsqrt_approx(float x) {
    float r; asm("sqrt.approx.f32 %0, %1;" : "=f"(r) : "f"(x)); return r;
}
__device__ __forceinline__ ull pack2(float lo, float hi) {
    ull r; asm("mov.b64 %0, {%1, %2};" : "=l"(r) : "f"(lo), "f"(hi)); return r;
}
__device__ __forceinline__ float2 unpack2(ull v) {
    float2 r; asm("mov.b64 {%0, %1}, %2;" : "=f"(r.x), "=f"(r.y) : "l"(v)); return r;
}
__device__ __forceinline__ void ffma2(ull& d, ull a, ull b) {
    asm("fma.rn.f32x2 %0, %1, %2, %0;" : "+l"(d) : "l"(a), "l"(b));
}
__device__ __forceinline__ int ld_acq(const int* p) {
    int v; asm volatile("ld.global.acquire.gpu.b32 %0, [%1];" : "=r"(v) : "l"(p)); return v;
}
__device__ __forceinline__ void st_rel(int* p, int v) {
    asm volatile("st.global.release.gpu.b32 [%0], %1;" :: "l"(p), "r"(v) : "memory");
}

__device__ __forceinline__ float2 bilinq(const float4* __restrict__ plane, float y, float x) {
    y = fminf(fmaxf(y, 0.f), CLIPMAX);
    x = fminf(fmaxf(x, 0.f), CLIPMAX);
    float fy = floorf(y), fx = floorf(x);
    int   y0 = (int)fy,  x0 = (int)fx;
    float wy = y - fy,   wx = x - fx;
    const float4* p = plane + y0 * WW + x0;
    float4 qa = __ldg(p);      // cross-launch read-only: nc path is safe here
    float4 qb = __ldg(p + 1);
    float w00 = (1.f - wy) * (1.f - wx);
    float w01 = (1.f - wy) * wx;
    float w10 = wy * (1.f - wx);
    float w11 = wy * wx;
    float2 r;
    r.x = qa.x * w00 + qb.x * w01 + qa.z * w10 + qb.z * w11;
    r.y = qa.y * w00 + qb.y * w01 + qa.w * w10 + qb.w * w11;
    return r;
}

// ---------------- kernel 1: conv + matgen (unchanged structure) ----------------
__global__ void __launch_bounds__(256) prep_kernel(const float* __restrict__ pred) {
    const int bid = blockIdx.x;
    const int tid = threadIdx.x;

    if (bid < 576) {
        __shared__ float2 tile[40][40];
        __shared__ float4 hs[40][32];

        const int bx = (bid % 12) * 32;
        const int by = ((bid / 12) % 12) * 32;
        const int b  = bid / 144;
        const float* img = pred + b * HH * WW;

        for (int i = tid; i < 40 * 40; i += 256) {
            int ly = i / 40, lx = i % 40;
            int gy = by - RAD + ly, gx = bx - RAD + lx;
            float v = (gy >= 0 && gy < HH && gx >= 0 && gx < WW) ? img[gy * WW + gx] : 0.f;
            tile[ly][lx] = make_float2(v, fabsf(v));
        }
        __syncthreads();

        for (int i = tid; i < 40 * 32; i += 256) {
            int r = i >> 5, c = i & 31;
            float hgp = 0.f, hdp = 0.f, hga = 0.f, hda = 0.f;
#pragma unroll
            for (int kx = 0; kx < 9; kx++) {
                float2 v = tile[r][c + kx];
                hgp = fmaf(C_G[kx],  v.x, hgp);
                hdp = fmaf(C_DG[kx], v.x, hdp);
                hga = fmaf(C_G[kx],  v.y, hga);
                hda = fmaf(C_DG[kx], v.y, hda);
            }
            hs[r][c] = make_float4(hgp, hdp, hga, hda);
        }
        __syncthreads();

        const int tx = tid & 31, ty = tid >> 5;
#pragma unroll
        for (int s4 = 0; s4 < 4; s4++) {
            int oy = ty + s4 * 8;
            float c0p = 0.f, c1p = 0.f, c0a = 0.f, c1a = 0.f;
#pragma unroll
            for (int ky = 0; ky < 9; ky++) {
                float4 h = hs[oy + ky][tx];
                c0p = fmaf(C_DG[ky], h.x, c0p);
                c1p = fmaf(C_G[ky],  h.y, c1p);
                c0a = fmaf(C_DG[ky], h.z, c0a);
                c1a = fmaf(C_G[ky],  h.w, c1a);
            }
            const int yg = by + oy, xg = bx + tx;
            const int o  = (b * HH + yg) * WW + xg;
            float2 Gv  = make_float2(10.f * c0p, 10.f * c1p);
            float2 GWv = make_float2(10.f * c0a, 10.f * c1a);
            reinterpret_cast<float2*>(&g_Gq [o])[0] = Gv;
            reinterpret_cast<float2*>(&g_GWq[o])[0] = GWv;
            if (yg > 0) {
                reinterpret_cast<float2*>(&g_Gq [o - WW])[1] = Gv;
                reinterpret_cast<float2*>(&g_GWq[o - WW])[1] = GWv;
            }
        }
    } else {
        __shared__ float am[2][NN], aw[2][NN];
        const int h = tid >> 7;
        const int i = (bid - 576) * 2 + h;
        const int j = tid & 127;
        {
            int k = j;
            float lam = 2.f - 2.f * cospif((float)k / 128.f);
            float c2  = (k == 0 ? 1.f : 2.f) / 128.f;
            float dm  = 1.f / (1.f + 0.001f * lam + 0.001f * lam * lam);
            float dw  = 1.f / (1.f + 0.001f * lam);
            float a   = cospif((float)(k * (2 * i + 1)) / 256.f);
            am[h][k] = c2 * dm * a;
            aw[h][k] = c2 * dw * a;
        }
        __syncthreads();
        float sm = 0.f, sw = 0.f;
#pragma unroll 4
        for (int k = 0; k < NN; k++) {
            float bq = cospif((float)(k * (2 * j + 1)) / 256.f);
            sm = fmaf(am[h][k], bq, sm);
            sw = fmaf(aw[h][k], bq, sw);
        }
        g_M [i * NN + j] = sm;
        g_Mw[i * NN + j] = sw;
    }
}

// ---------------- kernel 2: snake (4 blocks) + render (576 blocks) fused ----------------
// snake = bid [0,4); render = bid [4,580), rid = bid-4, b = rid/144.
// Render spins (2us backoff) on g_snakeflag[b] (release/acquire). All 580
// blocks are wave-1 resident -> no scheduling deadlock possible.
__global__ void __launch_bounds__(256) snake_render_kernel(const float* __restrict__ pred,
                                                           const float* __restrict__ nodes,
                                                           float* __restrict__ out) {
    const int bid = blockIdx.x;
    const int tid = threadIdx.x;

    if (bid < 4) {
        // ================= snake (identical to R7) =================
        const int b = bid;
        const int i = tid >> 1;
        const int h = tid & 1;

        __shared__ __align__(16) float2 v2pad[2][NN + 2 * HB];
        __shared__ __align__(16) float  vwpad[2][NN + 2 * HB];

        if (tid < HB) {
#pragma unroll
            for (int s = 0; s < 2; s++) {
                v2pad[s][tid] = make_float2(0.f, 0.f);
                v2pad[s][NN + HB + tid] = make_float2(0.f, 0.f);
                vwpad[s][tid] = 0.f;
                vwpad[s][NN + HB + tid] = 0.f;
            }
        }

        ull   Mp[9];
        float Mwr[9];
#pragma unroll
        for (int uu = 0; uu < 9; uu++) {
            int u = 2 * uu + h;
            float m = 0.f, mw = 0.f;
            if (u < BW) {
                int j = i - HB + u;
                bool ok = (j >= 0) && (j < NN);
                m  = ok ? __ldg(&g_M [i * NN + j]) : 0.f;   // cross-launch, safe
                mw = ok ? __ldg(&g_Mw[i * NN + j]) : 0.f;
            }
            Mp[uu]  = pack2(m, m);
            Mwr[uu] = mw;
        }

        const float4* Gb    = g_Gq  + b * HH * WW;
        const float4* GWb   = g_GWq + b * HH * WW;
        const float4* plane = h ? GWb : Gb;

        float2 p = make_float2(__ldg(&nodes[(b * NN + i) * 2]), __ldg(&nodes[(b * NN + i) * 2 + 1]));
        float  wd = 1.f;

        float2 gres = bilinq(plane, p.x, p.y);
        __syncthreads();

#pragma unroll 2
        for (int k = 1; k <= NSTEPS; k++) {
            const int buf = k & 1;
            if (h == 0)
                v2pad[buf][HB + i] = make_float2(p.x + 0.1f * gres.x, p.y + 0.1f * gres.y);
            else
                vwpad[buf][HB + i] = wd + 0.1f * sqrtf(gres.x * gres.x + gres.y * gres.y);
            __syncthreads();

            const ull* v2u = reinterpret_cast<const ull*>(v2pad[buf]);
            ull acc = 0ull;
#pragma unroll
            for (int uu = 0; uu < 9; uu++) {
                int u = 2 * uu + h;
                if (u < BW) ffma2(acc, Mp[uu], v2u[i + u]);
            }
            float2 pa = unpack2(acc);
            pa.x += __shfl_xor_sync(0xffffffffu, pa.x, 1);
            pa.y += __shfl_xor_sync(0xffffffffu, pa.y, 1);
            p = pa;

            gres = bilinq(plane, p.x, p.y);

            const float* vw = vwpad[buf];
            float wacc = 0.f;
#pragma unroll
            for (int uu = 0; uu < 9; uu++) {
                int u = 2 * uu + h;
                if (u < BW) wacc = fmaf(Mwr[uu], vw[i + u], wacc);
            }
            wacc += __shfl_xor_sync(0xffffffffu, wacc, 1);
            if (k > 1) wd = wacc;
        }

        {
            const int buf = (NSTEPS + 1) & 1;
            if (h == 1)
                vwpad[buf][HB + i] = wd + 0.1f * sqrtf(gres.x * gres.x + gres.y * gres.y);
            __syncthreads();
            const float* vw = vwpad[buf];
            float wacc = 0.f;
#pragma unroll
            for (int uu = 0; uu < 9; uu++) {
                int u = 2 * uu + h;
                if (u < BW) wacc = fmaf(Mwr[uu], vw[i + u], wacc);
            }
            wacc += __shfl_xor_sync(0xffffffffu, wacc, 1);
            wd = wacc;
        }

        if (h == 0) g_pts[b * NN + i] = p;
        else        g_wid[b * NN + i] = wd;
        __threadfence();
        __syncthreads();
        if (tid == 0) st_rel(&g_snakeflag[b], 1);

    } else {
        // ================= render =================
        const int rid = bid - 4;
        const int b   = rid / 144;
        const int tl  = rid % 144;
        const int x0  = (tl % 12) * 32;
        const int y0  = (tl / 12) * 32;
        const int t   = tid;

        __shared__ float4 keep[NN];
        __shared__ float  ur[NN];
        __shared__ int    wcnt[4], wofs[4], cnt;
        __shared__ float  ublim;

        if (t == 0) {
            while (ld_acq(&g_snakeflag[b]) == 0) __nanosleep(2000);
        }
        __syncthreads();

        float lb = 0.f; float4 nd = make_float4(0, 0, 0, 0); unsigned bmask = 0; bool pred_k = false;
        const float cy = (float)y0 + 15.5f, cx = (float)x0 + 15.5f;
        const float R = 21.95f;
        if (t < NN) {
            float2 p = g_pts[b * NN + t];   // plain coherent load after acquire
            float w  = g_wid[b * NN + t];
            nd = make_float4(p.x, p.y, w, 0.f);
            float dy = p.x - cy, dx = p.y - cx;
            float cd = sqrtf(dy * dy + dx * dx);
            lb = cd - R - w;
            ur[t] = cd + R - w;
        }
        __syncthreads();
        if (t < 64) ur[t] = fminf(ur[t], ur[t + 64]);
        __syncthreads();
        if (t < 32) {
            float v = fminf(ur[t], ur[t + 32]);
#pragma unroll
            for (int s = 16; s > 0; s >>= 1) v = fminf(v, __shfl_xor_sync(0xffffffffu, v, s));
            if (t == 0) ublim = fminf(v, 15.0f) + 0.02f;
        }
        __syncthreads();

        if (t < NN) {
            pred_k = lb < ublim;
            bmask = __ballot_sync(0xffffffffu, pred_k);
            if ((t & 31) == 0) wcnt[t >> 5] = __popc(bmask);
        }
        __syncthreads();
        if (t == 0) {
            int o = 0;
#pragma unroll
            for (int w = 0; w < 4; w++) { wofs[w] = o; o += wcnt[w]; }
            cnt = o;
        }
        __syncthreads();
        if (t < NN && pred_k) {
            int pos = wofs[t >> 5] + __popc(bmask & ((1u << (t & 31)) - 1u));
            keep[pos] = nd;
        }
        __syncthreads();

        const int n = cnt;
        const int y  = y0 + (t >> 3);
        const int xg = x0 + (t & 7) * 4;
        const float fy = (float)y, fx0 = (float)xg;
        const float mub = ublim;
        float m0 = mub, m1 = mub, m2 = mub, m3 = mub;

        for (int k = 0; k < n; k++) {
            float4 kk = keep[k];
            float dy  = fy - kk.x;
            float dy2 = dy * dy;
            float dx0 = fx0 - kk.y;
            float dx1 = dx0 + 1.f, dx2 = dx0 + 2.f, dx3 = dx0 + 3.f;
            float d20 = fmaf(dx0, dx0, dy2);
            float d21 = fmaf(dx1, dx1, dy2);
            float d22 = fmaf(dx2, dx2, dy2);
            float d23 = fmaf(dx3, dx3, dy2);
            float t0 = m0 + kk.z, t1 = m1 + kk.z, t2 = m2 + kk.z, t3 = m3 + kk.z;
            bool imp = (t0 > 0.f && d20 < t0 * t0) || (t1 > 0.f && d21 < t1 * t1) ||
                       (t2 > 0.f && d22 < t2 * t2) || (t3 > 0.f && d23 < t3 * t3);
            if (__any_sync(0xffffffffu, imp)) {
                m0 = fminf(m0, fsqrt_approx(d20) - kk.z);
                m1 = fminf(m1, fsqrt_approx(d21) - kk.z);
                m2 = fminf(m2, fsqrt_approx(d22) - kk.z);
                m3 = fminf(m3, fsqrt_approx(d23) - kk.z);
            }
        }
        m0 = fminf(fmaxf(m0, 0.f), 15.f);
        m1 = fminf(fmaxf(m1, 0.f), 15.f);
        m2 = fminf(fmaxf(m2, 0.f), 15.f);
        m3 = fminf(fmaxf(m3, 0.f), 15.f);

        const float4 pv = *reinterpret_cast<const float4*>(pred + (b * HH + y) * WW + xg);
        float e0 = pv.x - m0, e1 = pv.y - m1, e2 = pv.z - m2, e3 = pv.w - m3;
        float e = e0 * e0 + e1 * e1 + e2 * e2 + e3 * e3;

        __shared__ float red[256];
        red[t] = e;
        __syncthreads();
        if (t < 128) red[t] += red[t + 128];
        __syncthreads();
        if (t < 64) red[t] += red[t + 64];
        __syncthreads();
        if (t < 32) {
            float v = red[t] + red[t + 32];
#pragma unroll
            for (int s = 16; s > 0; s >>= 1) v += __shfl_down_sync(0xffffffffu, v, s);
            if (t == 0) g_part[(b * 12 + (tl / 12)) * 12 + (tl % 12)] = v;
        }

        __shared__ bool amLast;
        if (t == 0) {
            __threadfence();
            unsigned v = atomicAdd(&g_cnt, 1u);
            amLast = (v == 575u);
        }
        __syncthreads();
        if (amLast) {
            __shared__ double sh[256];
            double s = 0.0;
            for (int idx = t; idx < 576; idx += 256) s += (double)g_part[idx];
            sh[t] = s;
            __syncthreads();
            for (int st = 128; st > 0; st >>= 1) {
                if (t < st) sh[t] += sh[t + st];
                __syncthreads();
            }
            if (t == 0) {
                out[0] = (float)(sh[0] / (double)(BATCH * HH * WW));
                g_cnt = 0u;
#pragma unroll
                for (int q = 0; q < BATCH; q++) g_snakeflag[q] = 0;
            }
        }
    }
}

// ---------------- launcher ----------------
extern "C" void kernel_launch(void* const* d_in, const int* in_sizes, int n_in,
                              void* d_out, int out_size) {
    const float* pred  = (const float*)d_in[0];
    const float* nodes = (const float*)d_in[1];
    float* out = (float*)d_out;
    (void)in_sizes; (void)n_in; (void)out_size;

    prep_kernel<<<640, 256>>>(pred);
    snake_render_kernel<<<580, 256>>>(pred, nodes, out);
}

// round 11
// speedup vs baseline: 1.1283x; 1.1036x over previous
#include <cuda_runtime.h>
#include <cuda_fp16.h>
#include <cstdint>

#define BATCH 4
#define HH 384
#define WW 384
#define NN 128
#define RAD 4
#define NSTEPS 50
#define CLIPMAX 382.999f
#define HB 8
#define BW (2 * HB + 1)

// ---------------- scratch ----------------
// fp16 packed quad planes: entry (y,x) = 8 halves {gy,gx} at (y,x),(y,x+1),(y+1,x),(y+1,x+1)
__device__ uint4 g_Gh [BATCH * HH * WW];
__device__ uint4 g_GWh[BATCH * HH * WW];
__device__ float  g_M [NN * NN];
__device__ float  g_Mw[NN * NN];
__device__ float2 g_pts[BATCH * NN];
__device__ float  g_wid[BATCH * NN];
__device__ float  g_part[576];
__device__ unsigned g_cnt;

typedef unsigned long long ull;

__device__ __constant__ float C_G[9] = {
    0.027630550874912204f, 0.06628226552596338f, 0.12383156996112883f,
    0.18017411419619135f,  0.20416299888360846f, 0.18017411419619135f,
    0.12383156996112883f,  0.06628226552596338f, 0.027630550874912204f };
__device__ __constant__ float C_DG[9] = {
    0.027630550874912204f,  0.049711699144472535f,  0.061915784980564414f,
    0.04504352854904784f,   0.0f,                  -0.04504352854904784f,
   -0.061915784980564414f, -0.049711699144472535f, -0.027630550874912204f };

__device__ __forceinline__ float fsqrt_approx(float x) {
    float r; asm("sqrt.approx.f32 %0, %1;" : "=f"(r) : "f"(x)); return r;
}
__device__ __forceinline__ ull pack2(float lo, float hi) {
    ull r; asm("mov.b64 %0, {%1, %2};" : "=l"(r) : "f"(lo), "f"(hi)); return r;
}
__device__ __forceinline__ float2 unpack2(ull v) {
    float2 r; asm("mov.b64 {%0, %1}, %2;" : "=f"(r.x), "=f"(r.y) : "l"(v)); return r;
}
__device__ __forceinline__ void ffma2(ull& d, ull a, ull b) {
    asm("fma.rn.f32x2 %0, %1, %2, %0;" : "+l"(d) : "l"(a), "l"(b));
}

// fp16 quad bilinear: ONE LDG.128 per tap
__device__ __forceinline__ float2 bilin_h(const uint4* __restrict__ plane, float y, float x) {
    y = fminf(fmaxf(y, 0.f), CLIPMAX);
    x = fminf(fmaxf(x, 0.f), CLIPMAX);
    float fy = floorf(y), fx = floorf(x);
    int   y0 = (int)fy,  x0 = (int)fx;
    float wy = y - fy,   wx = x - fx;
    uint4 q = __ldg(plane + y0 * WW + x0);
    const __half2* h = reinterpret_cast<const __half2*>(&q);
    float2 q00 = __half22float2(h[0]);
    float2 q01 = __half22float2(h[1]);
    float2 q10 = __half22float2(h[2]);
    float2 q11 = __half22float2(h[3]);
    float w00 = (1.f - wy) * (1.f - wx);
    float w01 = (1.f - wy) * wx;
    float w10 = wy * (1.f - wx);
    float w11 = wy * wx;
    float2 r;
    r.x = q00.x * w00 + q01.x * w01 + q10.x * w10 + q11.x * w11;
    r.y = q00.y * w00 + q01.y * w01 + q10.y * w10 + q11.y * w11;
    return r;
}

// ---------------- kernel 1: separable conv -> fp16 quad planes, + matgen ----------------
__global__ void __launch_bounds__(256) prep_kernel(const float* __restrict__ pred) {
    const int bid = blockIdx.x;
    const int tid = threadIdx.x;

    if (bid < 576) {
        // tile covers rows/cols [b-4, b+37): 41x41 so output row/col 32 (quad halo) is computable
        __shared__ union { float2 tile[41][41]; float4 res[34][34]; } U;
        __shared__ float4 hs[41][33];

        const int bx = (bid % 12) * 32;
        const int by = ((bid / 12) % 12) * 32;
        const int b  = bid / 144;
        const float* img = pred + b * HH * WW;

        for (int i = tid; i < 41 * 41; i += 256) {
            int ly = i / 41, lx = i % 41;
            int gy = by - RAD + ly, gx = bx - RAD + lx;
            float v = (gy >= 0 && gy < HH && gx >= 0 && gx < WW) ? img[gy * WW + gx] : 0.f;
            U.tile[ly][lx] = make_float2(v, fabsf(v));
        }
        __syncthreads();

        // horizontal pass: 41 rows x 33 cols
        for (int i = tid; i < 41 * 33; i += 256) {
            int r = i / 33, c = i % 33;
            float hgp = 0.f, hdp = 0.f, hga = 0.f, hda = 0.f;
#pragma unroll
            for (int kx = 0; kx < 9; kx++) {
                float2 v = U.tile[r][c + kx];
                hgp = fmaf(C_G[kx],  v.x, hgp);
                hdp = fmaf(C_DG[kx], v.x, hdp);
                hga = fmaf(C_G[kx],  v.y, hga);
                hda = fmaf(C_DG[kx], v.y, hda);
            }
            hs[r][c] = make_float4(hgp, hdp, hga, hda);
        }
        __syncthreads();   // hs done; tile dead -> res may reuse the union

        // vertical pass: 33x33 results (x10 scaling folded in)
        for (int i = tid; i < 33 * 33; i += 256) {
            int r = i / 33, c = i % 33;
            float c0p = 0.f, c1p = 0.f, c0a = 0.f, c1a = 0.f;
#pragma unroll
            for (int ky = 0; ky < 9; ky++) {
                float4 h = hs[r + ky][c];
                c0p = fmaf(C_DG[ky], h.x, c0p);
                c1p = fmaf(C_G[ky],  h.y, c1p);
                c0a = fmaf(C_DG[ky], h.z, c0a);
                c1a = fmaf(C_G[ky],  h.w, c1a);
            }
            U.res[r][c] = make_float4(10.f * c0p, 10.f * c1p, 10.f * c0a, 10.f * c1a);
        }
        __syncthreads();

        // pack fp16 quads: one 16B store per pixel per plane
        const int tx = tid & 31, ty = tid >> 5;
#pragma unroll
        for (int s4 = 0; s4 < 4; s4++) {
            int oy = ty + s4 * 8;
            float4 A = U.res[oy][tx],     B = U.res[oy][tx + 1];
            float4 C = U.res[oy + 1][tx], D = U.res[oy + 1][tx + 1];
            uint4 qg, qw;
            __half2* pg = reinterpret_cast<__half2*>(&qg);
            __half2* pw = reinterpret_cast<__half2*>(&qw);
            pg[0] = __float22half2_rn(make_float2(A.x, A.y));
            pg[1] = __float22half2_rn(make_float2(B.x, B.y));
            pg[2] = __float22half2_rn(make_float2(C.x, C.y));
            pg[3] = __float22half2_rn(make_float2(D.x, D.y));
            pw[0] = __float22half2_rn(make_float2(A.z, A.w));
            pw[1] = __float22half2_rn(make_float2(B.z, B.w));
            pw[2] = __float22half2_rn(make_float2(C.z, C.w));
            pw[3] = __float22half2_rn(make_float2(D.z, D.w));
            const int o = (b * HH + by + oy) * WW + bx + tx;
            g_Gh [o] = qg;
            g_GWh[o] = qw;
        }
    } else {
        // ---- matgen ----
        __shared__ float am[2][NN], aw[2][NN];
        const int h = tid >> 7;
        const int i = (bid - 576) * 2 + h;
        const int j = tid & 127;
        if (bid == 576 && tid == 0) g_cnt = 0;
        {
            int k = j;
            float lam = 2.f - 2.f * cospif((float)k / 128.f);
            float c2  = (k == 0 ? 1.f : 2.f) / 128.f;
            float dm  = 1.f / (1.f + 0.001f * lam + 0.001f * lam * lam);
            float dw  = 1.f / (1.f + 0.001f * lam);
            float a   = cospif((float)(k * (2 * i + 1)) / 256.f);
            am[h][k] = c2 * dm * a;
            aw[h][k] = c2 * dw * a;
        }
        __syncthreads();
        float sm = 0.f, sw = 0.f;
#pragma unroll 4
        for (int k = 0; k < NN; k++) {
            float bq = cospif((float)(k * (2 * j + 1)) / 256.f);
            sm = fmaf(am[h][k], bq, sm);
            sw = fmaf(aw[h][k], bq, sw);
        }
        g_M [i * NN + j] = sm;
        g_Mw[i * NN + j] = sw;
    }
}

// ---------------- kernel 2: snake (R7 pipelined pair-split; 1 LDG per gather) ----------------
__global__ void __launch_bounds__(256) snake_kernel(const float* __restrict__ nodes) {
    const int b   = blockIdx.x;
    const int tid = threadIdx.x;
    const int i   = tid >> 1;
    const int h   = tid & 1;

    __shared__ __align__(16) float2 v2pad[2][NN + 2 * HB];
    __shared__ __align__(16) float  vwpad[2][NN + 2 * HB];

    if (tid < HB) {
#pragma unroll
        for (int s = 0; s < 2; s++) {
            v2pad[s][tid] = make_float2(0.f, 0.f);
            v2pad[s][NN + HB + tid] = make_float2(0.f, 0.f);
            vwpad[s][tid] = 0.f;
            vwpad[s][NN + HB + tid] = 0.f;
        }
    }

    ull   Mp[9];
    float Mwr[9];
#pragma unroll
    for (int uu = 0; uu < 9; uu++) {
        int u = 2 * uu + h;
        float m = 0.f, mw = 0.f;
        if (u < BW) {
            int j = i - HB + u;
            bool ok = (j >= 0) && (j < NN);
            m  = ok ? __ldg(&g_M [i * NN + j]) : 0.f;
            mw = ok ? __ldg(&g_Mw[i * NN + j]) : 0.f;
        }
        Mp[uu]  = pack2(m, m);
        Mwr[uu] = mw;
    }

    const uint4* Gb    = g_Gh  + b * HH * WW;
    const uint4* GWb   = g_GWh + b * HH * WW;
    const uint4* plane = h ? GWb : Gb;

    float2 p = make_float2(__ldg(&nodes[(b * NN + i) * 2]), __ldg(&nodes[(b * NN + i) * 2 + 1]));
    float  wd = 1.f;

    float2 gres = bilin_h(plane, p.x, p.y);
    __syncthreads();

#pragma unroll 2
    for (int k = 1; k <= NSTEPS; k++) {
        const int buf = k & 1;
        if (h == 0)
            v2pad[buf][HB + i] = make_float2(p.x + 0.1f * gres.x, p.y + 0.1f * gres.y);
        else
            vwpad[buf][HB + i] = wd + 0.1f * sqrtf(gres.x * gres.x + gres.y * gres.y);
        __syncthreads();

        const ull* v2u = reinterpret_cast<const ull*>(v2pad[buf]);
        ull acc = 0ull;
#pragma unroll
        for (int uu = 0; uu < 9; uu++) {
            int u = 2 * uu + h;
            if (u < BW) ffma2(acc, Mp[uu], v2u[i + u]);
        }
        float2 pa = unpack2(acc);
        pa.x += __shfl_xor_sync(0xffffffffu, pa.x, 1);
        pa.y += __shfl_xor_sync(0xffffffffu, pa.y, 1);
        p = pa;

        gres = bilin_h(plane, p.x, p.y);

        const float* vw = vwpad[buf];
        float wacc = 0.f;
#pragma unroll
        for (int uu = 0; uu < 9; uu++) {
            int u = 2 * uu + h;
            if (u < BW) wacc = fmaf(Mwr[uu], vw[i + u], wacc);
        }
        wacc += __shfl_xor_sync(0xffffffffu, wacc, 1);
        if (k > 1) wd = wacc;
    }

    {
        const int buf = (NSTEPS + 1) & 1;
        if (h == 1)
            vwpad[buf][HB + i] = wd + 0.1f * sqrtf(gres.x * gres.x + gres.y * gres.y);
        __syncthreads();
        const float* vw = vwpad[buf];
        float wacc = 0.f;
#pragma unroll
        for (int uu = 0; uu < 9; uu++) {
            int u = 2 * uu + h;
            if (u < BW) wacc = fmaf(Mwr[uu], vw[i + u], wacc);
        }
        wacc += __shfl_xor_sync(0xffffffffu, wacc, 1);
        wd = wacc;
    }

    if (h == 0) g_pts[b * NN + i] = p;
    else        g_wid[b * NN + i] = wd;
}

// ---------------- kernel 3: render + shortlist + fused final reduce (R7) ----------------
__global__ void __launch_bounds__(256) render_kernel(const float* __restrict__ pred,
                                                     float* __restrict__ out) {
    const int b  = blockIdx.z;
    const int x0 = blockIdx.x * 32;
    const int y0 = blockIdx.y * 32;
    const int t  = threadIdx.x;

    __shared__ float4 keep[NN];
    __shared__ float  ur[NN];
    __shared__ int    wcnt[4], wofs[4], cnt;
    __shared__ float  ublim;

    float lb = 0.f; float4 nd = make_float4(0, 0, 0, 0); unsigned bmask = 0; bool pred_k = false;
    const float cy = (float)y0 + 15.5f, cx = (float)x0 + 15.5f;
    const float R = 21.95f;
    if (t < NN) {
        float2 p = g_pts[b * NN + t];
        float w  = g_wid[b * NN + t];
        nd = make_float4(p.x, p.y, w, 0.f);
        float dy = p.x - cy, dx = p.y - cx;
        float cd = sqrtf(dy * dy + dx * dx);
        lb = cd - R - w;
        ur[t] = cd + R - w;
    }
    __syncthreads();
    if (t < 64) ur[t] = fminf(ur[t], ur[t + 64]);
    __syncthreads();
    if (t < 32) {
        float v = fminf(ur[t], ur[t + 32]);
#pragma unroll
        for (int s = 16; s > 0; s >>= 1) v = fminf(v, __shfl_xor_sync(0xffffffffu, v, s));
        if (t == 0) ublim = fminf(v, 15.0f) + 0.02f;
    }
    __syncthreads();

    if (t < NN) {
        pred_k = lb < ublim;
        bmask = __ballot_sync(0xffffffffu, pred_k);
        if ((t & 31) == 0) wcnt[t >> 5] = __popc(bmask);
    }
    __syncthreads();
    if (t == 0) {
        int o = 0;
#pragma unroll
        for (int w = 0; w < 4; w++) { wofs[w] = o; o += wcnt[w]; }
        cnt = o;
    }
    __syncthreads();
    if (t < NN && pred_k) {
        int pos = wofs[t >> 5] + __popc(bmask & ((1u << (t & 31)) - 1u));
        keep[pos] = nd;
    }
    __syncthreads();

    const int n = cnt;
    const int y  = y0 + (t >> 3);
    const int xg = x0 + (t & 7) * 4;
    const float fy = (float)y, fx0 = (float)xg;
    const float mub = ublim;
    float m0 = mub, m1 = mub, m2 = mub, m3 = mub;

    for (int k = 0; k < n; k++) {
        float4 kk = keep[k];
        float dy  = fy - kk.x;
        float dy2 = dy * dy;
        float dx0 = fx0 - kk.y;
        float dx1 = dx0 + 1.f, dx2 = dx0 + 2.f, dx3 = dx0 + 3.f;
        float d20 = fmaf(dx0, dx0, dy2);
        float d21 = fmaf(dx1, dx1, dy2);
        float d22 = fmaf(dx2, dx2, dy2);
        float d23 = fmaf(dx3, dx3, dy2);
        float t0 = m0 + kk.z, t1 = m1 + kk.z, t2 = m2 + kk.z, t3 = m3 + kk.z;
        bool imp = (t0 > 0.f && d20 < t0 * t0) || (t1 > 0.f && d21 < t1 * t1) ||
                   (t2 > 0.f && d22 < t2 * t2) || (t3 > 0.f && d23 < t3 * t3);
        if (__any_sync(0xffffffffu, imp)) {
            m0 = fminf(m0, fsqrt_approx(d20) - kk.z);
            m1 = fminf(m1, fsqrt_approx(d21) - kk.z);
            m2 = fminf(m2, fsqrt_approx(d22) - kk.z);
            m3 = fminf(m3, fsqrt_approx(d23) - kk.z);
        }
    }
    m0 = fminf(fmaxf(m0, 0.f), 15.f);
    m1 = fminf(fmaxf(m1, 0.f), 15.f);
    m2 = fminf(fmaxf(m2, 0.f), 15.f);
    m3 = fminf(fmaxf(m3, 0.f), 15.f);

    const float4 pv = *reinterpret_cast<const float4*>(pred + (b * HH + y) * WW + xg);
    float e0 = pv.x - m0, e1 = pv.y - m1, e2 = pv.z - m2, e3 = pv.w - m3;
    float e = e0 * e0 + e1 * e1 + e2 * e2 + e3 * e3;

    __shared__ float red[256];
    red[t] = e;
    __syncthreads();
    if (t < 128) red[t] += red[t + 128];
    __syncthreads();
    if (t < 64) red[t] += red[t + 64];
    __syncthreads();
    if (t < 32) {
        float v = red[t] + red[t + 32];
#pragma unroll
        for (int s = 16; s > 0; s >>= 1) v += __shfl_down_sync(0xffffffffu, v, s);
        if (t == 0) g_part[(b * 12 + blockIdx.y) * 12 + blockIdx.x] = v;
    }

    __shared__ bool amLast;
    if (t == 0) {
        __threadfence();
        unsigned v = atomicAdd(&g_cnt, 1u);
        amLast = (v == 575u);
    }
    __syncthreads();
    if (amLast) {
        __shared__ double sh[256];
        double s = 0.0;
        for (int idx = t; idx < 576; idx += 256) s += (double)g_part[idx];
        sh[t] = s;
        __syncthreads();
        for (int st = 128; st > 0; st >>= 1) {
            if (t < st) sh[t] += sh[t + st];
            __syncthreads();
        }
        if (t == 0) out[0] = (float)(sh[0] / (double)(BATCH * HH * WW));
    }
}

// ---------------- launcher ----------------
extern "C" void kernel_launch(void* const* d_in, const int* in_sizes, int n_in,
                              void* d_out, int out_size) {
    const float* pred  = (const float*)d_in[0];
    const float* nodes = (const float*)d_in[1];
    float* out = (float*)d_out;
    (void)in_sizes; (void)n_in; (void)out_size;

    prep_kernel<<<640, 256>>>(pred);
    snake_kernel<<<BATCH, 256>>>(nodes);
    render_kernel<<<dim3(12, 12, BATCH), 256>>>(pred, out);
}